// round 2
// baseline (speedup 1.0000x reference)
#include <cuda_runtime.h>
#include <math.h>

#define B_  8
#define H_  384
#define W_  512
#define HW_ (H_ * W_)
#define NPIX (B_ * HW_)

// 5-tap taps: out[x] = K0*in[x-2] + K1*in[x-1] + 0*in[x] + K3*in[x+1] + K4*in[x+2]
#define K0 (-1.0f / 12.0f)
#define K1 (2.0f / 3.0f)
#define K3 (-2.0f / 3.0f)
#define K4 (1.0f / 12.0f)

// ---- scratch (module globals; no runtime allocation) ----
__device__ float  g_flowf[B_ * 2 * HW_];
__device__ float  g_flowb[B_ * 2 * HW_];
__device__ float  g_imgw [B_ * 3 * HW_];   // warped image, reused per direction
__device__ float  g_mask [NPIX];           // mask*occ, reused per direction
__device__ double g_acc[3];                // 0 = energy, 1 = entropy-sum, 2 = epe-sum

__device__ __forceinline__ float sigm(float x) { return 1.0f / (1.0f + expf(-x)); }

__device__ __forceinline__ void blockReduceAdd(double* dst, float v) {
    __shared__ float ws[32];
    int lane = threadIdx.x & 31;
    int wid  = threadIdx.x >> 5;
#pragma unroll
    for (int o = 16; o; o >>= 1) v += __shfl_down_sync(0xffffffffu, v, o);
    __syncthreads();                 // protect ws against a previous invocation
    if (lane == 0) ws[wid] = v;
    __syncthreads();
    if (wid == 0) {
        int nw = (blockDim.x + 31) >> 5;
        v = (lane < nw) ? ws[lane] : 0.0f;
#pragma unroll
        for (int o = 16; o; o >>= 1) v += __shfl_down_sync(0xffffffffu, v, o);
        if (lane == 0) atomicAdd(dst, (double)v);
    }
}

__global__ void zero_acc_kernel() {
    if (threadIdx.x < 3) g_acc[threadIdx.x] = 0.0;
}

// Pass 1: reparameterized flow samples + entropy sum + EPE sum
__global__ void sample_kernel(const float* __restrict__ mf, const float* __restrict__ lvf,
                              const float* __restrict__ nf,
                              const float* __restrict__ mb, const float* __restrict__ lvb,
                              const float* __restrict__ nb,
                              const float* __restrict__ tgt) {
    int p = blockIdx.x * blockDim.x + threadIdx.x;
    float ent = 0.0f, epe = 0.0f;
    if (p < NPIX) {
        int b = p / HW_;
        int r = p - b * HW_;
        int i0 = (b * 2) * HW_ + r;   // channel 0
        int i1 = i0 + HW_;            // channel 1
        float lf0 = lvf[i0], lf1 = lvf[i1];
        float lb0 = lvb[i0], lb1 = lvb[i1];
        float m0 = mf[i0], m1 = mf[i1];
        g_flowf[i0] = m0 + expf(0.5f * lf0) * nf[i0];
        g_flowf[i1] = m1 + expf(0.5f * lf1) * nf[i1];
        g_flowb[i0] = mb[i0] + expf(0.5f * lb0) * nb[i0];
        g_flowb[i1] = mb[i1] + expf(0.5f * lb1) * nb[i1];
        ent = lf0 + lf1 + lb0 + lb1;
        float d0 = m0 - tgt[i0];
        float d1 = m1 - tgt[i1];
        epe = sqrtf(d0 * d0 + d1 * d1);
    }
    blockReduceAdd(&g_acc[1], ent);
    blockReduceAdd(&g_acc[2], epe);
}

// Pass 2 (per direction): mask, occlusion, bilinear warps, data/fb/smooth/mask terms.
// Writes warped image + final mask to scratch for the gradient pass.
// dirn==0: flow_a = flowf, flow_b = flowb ; dirn==1: swapped.
__global__ void dir_kernel(const float* __restrict__ img_a,
                           const float* __restrict__ img_b, int dirn) {
    const float* __restrict__ flow_a = dirn ? g_flowb : g_flowf;
    const float* __restrict__ flow_b = dirn ? g_flowf : g_flowb;
    int p = blockIdx.x * blockDim.x + threadIdx.x;
    float e = 0.0f;
    if (p < NPIX) {
        int b = p / HW_;
        int r = p - b * HW_;
        int y = r / W_;
        int x = r - y * W_;
        int base2 = b * 2 * HW_ + r;

        float fa0 = flow_a[base2];
        float fa1 = flow_a[base2 + HW_];
        float xq = (float)x + fa0;
        float yq = (float)y + fa1;

        // border mask
        float mx = sigm(xq + 0.5f) * (1.0f - sigm(xq - ((float)W_ - 0.5f)));
        float my = sigm(yq + 0.5f) * (1.0f - sigm(yq - ((float)H_ - 0.5f)));
        float bmask = mx * my;

        // bilinear taps
        float x0f = floorf(xq), y0f = floorf(yq);
        float wx = xq - x0f, wy = yq - y0f;
        int x0 = (int)x0f, y0 = (int)y0f;
        int x1 = x0 + 1,   y1 = y0 + 1;
        float vx0 = (x0 >= 0 && x0 <= W_ - 1) ? 1.0f : 0.0f;
        float vx1 = (x1 >= 0 && x1 <= W_ - 1) ? 1.0f : 0.0f;
        float vy0 = (y0 >= 0 && y0 <= H_ - 1) ? 1.0f : 0.0f;
        float vy1 = (y1 >= 0 && y1 <= H_ - 1) ? 1.0f : 0.0f;
        float w00 = (1.0f - wx) * (1.0f - wy) * vx0 * vy0;
        float w10 = wx * (1.0f - wy) * vx1 * vy0;
        float w01 = (1.0f - wx) * wy * vx0 * vy1;
        float w11 = wx * wy * vx1 * vy1;
        int xc0 = min(max(x0, 0), W_ - 1), xc1 = min(max(x1, 0), W_ - 1);
        int yc0 = min(max(y0, 0), H_ - 1), yc1 = min(max(y1, 0), H_ - 1);
        int o00 = yc0 * W_ + xc0, o10 = yc0 * W_ + xc1;
        int o01 = yc1 * W_ + xc0, o11 = yc1 * W_ + xc1;

        // warp flow_b (2 channels)
        const float* fb0 = flow_b + (size_t)b * 2 * HW_;
        const float* fb1 = fb0 + HW_;
        float fw0 = w00 * fb0[o00] + w10 * fb0[o10] + w01 * fb0[o01] + w11 * fb0[o11];
        float fw1 = w00 * fb1[o00] + w10 * fb1[o10] + w01 * fb1[o01] + w11 * fb1[o11];

        float mag = fa0 * fa0 + fa1 * fa1 + fw0 * fw0 + fw1 * fw1;
        float d0 = fa0 + fw0, d1 = fa1 + fw1;
        float D = d0 * d0 + d1 * d1;
        float occ = 1.0f - sigm(D - (0.01f * mag + 0.5f));
        float m = bmask * occ;
        g_mask[p] = m;

        // warp img_b (3 channels) + data term
        const float* ib = img_b + (size_t)b * 3 * HW_;
        const float* ia = img_a + (size_t)b * 3 * HW_;
        float A = 0.0f;
#pragma unroll
        for (int c = 0; c < 3; c++) {
            const float* ibc = ib + c * HW_;
            float v = w00 * ibc[o00] + w10 * ibc[o10] + w01 * ibc[o01] + w11 * ibc[o11];
            g_imgw[(size_t)b * 3 * HW_ + c * HW_ + r] = v;
            float dd = ia[c * HW_ + r] - v;
            A += dd * dd;
        }

        e = (1.0f - m)                       // mask term
          + sqrtf(A + 1e-5f) * m             // data term
          + sqrtf(D + 1e-5f) * m;            // fb term

        // smoothness (first differences, zero-padded at far edges)
        float s = 0.0f;
        if (x < W_ - 1) {
            float a0 = flow_a[base2 + 1] - fa0;
            float a1 = flow_a[base2 + HW_ + 1] - fa1;
            s += a0 * a0 + a1 * a1;
        }
        if (y < H_ - 1) {
            float a0 = flow_a[base2 + W_] - fa0;
            float a1 = flow_a[base2 + HW_ + W_] - fa1;
            s += a0 * a0 + a1 * a1;
        }
        e += sqrtf(s + 1e-5f);
    }
    blockReduceAdd(&g_acc[0], e);
}

// Pass 3 (per direction): 5-tap gradient-constancy term using scratch imgw/mask
__global__ void grad_kernel(const float* __restrict__ img_a) {
    int p = blockIdx.x * blockDim.x + threadIdx.x;
    float e = 0.0f;
    if (p < NPIX) {
        int b = p / HW_;
        int r = p - b * HW_;
        int y = r / W_;
        int x = r - y * W_;
        float m = g_mask[p];
        const float* ia = img_a + (size_t)b * 3 * HW_;
        const float* iw = g_imgw + (size_t)b * 3 * HW_;
        float Ct = 0.0f;
#pragma unroll
        for (int c = 0; c < 3; c++) {
            const float* Ar = ia + c * HW_ + y * W_;   // row base
            const float* Wr = iw + c * HW_ + y * W_;
            float ga = 0.0f, gw = 0.0f;
            if (x >= 2)      { ga += K0 * Ar[x - 2]; gw += K0 * Wr[x - 2]; }
            if (x >= 1)      { ga += K1 * Ar[x - 1]; gw += K1 * Wr[x - 1]; }
            if (x + 1 < W_)  { ga += K3 * Ar[x + 1]; gw += K3 * Wr[x + 1]; }
            if (x + 2 < W_)  { ga += K4 * Ar[x + 2]; gw += K4 * Wr[x + 2]; }
            float dgx = ga - gw;
            Ct += dgx * dgx;

            const float* Ac = ia + c * HW_ + x;        // column base
            const float* Wc = iw + c * HW_ + x;
            ga = 0.0f; gw = 0.0f;
            if (y >= 2)      { ga += K0 * Ac[(y - 2) * W_]; gw += K0 * Wc[(y - 2) * W_]; }
            if (y >= 1)      { ga += K1 * Ac[(y - 1) * W_]; gw += K1 * Wc[(y - 1) * W_]; }
            if (y + 1 < H_)  { ga += K3 * Ac[(y + 1) * W_]; gw += K3 * Wc[(y + 1) * W_]; }
            if (y + 2 < H_)  { ga += K4 * Ac[(y + 2) * W_]; gw += K4 * Wc[(y + 2) * W_]; }
            float dgy = ga - gw;
            Ct += dgy * dgy;
        }
        e = sqrtf(Ct + 1e-5f) * m;
    }
    blockReduceAdd(&g_acc[0], e);
}

__global__ void finalize_kernel(float* __restrict__ out) {
    if (threadIdx.x == 0) {
        double energy  = g_acc[0];
        double entropy = 0.5 * g_acc[1];
        out[0] = (float)((energy - entropy) / (double)B_);
        out[1] = (float)(g_acc[2] / (double)NPIX);
    }
}

extern "C" void kernel_launch(void* const* d_in, const int* in_sizes, int n_in,
                              void* d_out, int out_size) {
    const float* meanf   = (const float*)d_in[0];
    const float* logvarf = (const float*)d_in[1];
    const float* meanb   = (const float*)d_in[2];
    const float* logvarb = (const float*)d_in[3];
    const float* img1    = (const float*)d_in[4];
    const float* img2    = (const float*)d_in[5];
    const float* target  = (const float*)d_in[6];
    const float* noisef  = (const float*)d_in[7];
    const float* noiseb  = (const float*)d_in[8];
    float* out = (float*)d_out;

    const int threads = 256;
    const int blocks = (NPIX + threads - 1) / threads;

    zero_acc_kernel<<<1, 32>>>();
    sample_kernel<<<blocks, threads>>>(meanf, logvarf, noisef,
                                       meanb, logvarb, noiseb, target);
    // forward direction: warp *_b by flowf, images (img1, img2)
    dir_kernel<<<blocks, threads>>>(img1, img2, 0);
    grad_kernel<<<blocks, threads>>>(img1);
    // backward direction: warp *_f by flowb, images (img2, img1)
    dir_kernel<<<blocks, threads>>>(img2, img1, 1);
    grad_kernel<<<blocks, threads>>>(img2);
    finalize_kernel<<<1, 32>>>(out);
}